// round 1
// baseline (speedup 1.0000x reference)
#include <cuda_runtime.h>
#include <math.h>

// features: (B=16, C=256, H=64, W=64) fp32, channel stride = 4096 floats
// out:      (B, H, W) fp32
// Per pixel: reduce over C -> mag/var/std (clipped), then 3->16->1 MLP + sigmoid.

#define C_DIM   256
#define HW      4096          // 64*64
#define NPIX    65536         // 16*64*64
#define TPB     256

__global__ void __launch_bounds__(TPB, 8)
fis_kernel(const float* __restrict__ f,
           const float* __restrict__ W1,   // (3,16) row-major (in,out) -> 48
           const float* __restrict__ b1,   // 16
           const float* __restrict__ W2,   // (16,1) -> 16
           const float* __restrict__ b2,   // 1
           float* __restrict__ out)
{
    __shared__ float sp[81];  // [0:48) W1, [48:64) b1, [64:80) W2, [80] b2
    int tid = threadIdx.x;
    if (tid < 81) {
        float v;
        if (tid < 48)      v = W1[tid];
        else if (tid < 64) v = b1[tid - 48];
        else if (tid < 80) v = W2[tid - 64];
        else               v = b2[0];
        sp[tid] = v;
    }
    __syncthreads();

    int p = blockIdx.x * TPB + tid;           // pixel id in [0, 65536)
    int b  = p >> 12;                          // / 4096
    int hw = p & (HW - 1);
    const float* __restrict__ src = f + (size_t)b * C_DIM * HW + hw;

    // ---- channel reduction (the whole memory cost) ----
    float s = 0.f, ss = 0.f;
    #pragma unroll 8
    for (int c = 0; c < C_DIM; ++c) {
        float v = __ldg(src + (size_t)c * HW);
        s  += v;
        ss  = fmaf(v, v, ss);
    }

    // ---- stats ----
    const float inv_c  = 1.0f / 256.0f;
    const float inv_c1 = 1.0f / 255.0f;
    float mag = sqrtf(ss * inv_c);                      // sqrt(mean(f^2))
    float var = (ss - s * s * inv_c) * inv_c1;          // unbiased (ddof=1)
    var = fmaxf(var, 0.0f);
    float sd  = sqrtf(var);

    float x0 = fminf(mag, 1.0f);
    float x1 = fminf(var, 1.0f);
    float x2 = fminf(sd,  1.0f);

    // ---- 3->16 relu, 16->1 sigmoid ----
    float acc = sp[80];   // b2
    #pragma unroll
    for (int o = 0; o < 16; ++o) {
        float h = sp[48 + o];                 // b1[o]
        h = fmaf(x0, sp[o],      h);          // W1[0][o]
        h = fmaf(x1, sp[16 + o], h);          // W1[1][o]
        h = fmaf(x2, sp[32 + o], h);          // W1[2][o]
        h = fmaxf(h, 0.0f);
        acc = fmaf(h, sp[64 + o], acc);       // W2[o]
    }
    out[p] = 1.0f / (1.0f + __expf(-acc));
}

extern "C" void kernel_launch(void* const* d_in, const int* in_sizes, int n_in,
                              void* d_out, int out_size)
{
    const float* f  = (const float*)d_in[0];
    const float* W1 = (const float*)d_in[1];
    const float* b1 = (const float*)d_in[2];
    const float* W2 = (const float*)d_in[3];
    const float* b2 = (const float*)d_in[4];
    float* out = (float*)d_out;

    fis_kernel<<<NPIX / TPB, TPB>>>(f, W1, b1, W2, b2, out);
}